// round 1
// baseline (speedup 1.0000x reference)
#include <cuda_runtime.h>
#include <math.h>

// ---------------------------------------------------------------------------
// WindowsLite2MSA: fused windows + grouped qkv conv + 5x5 avgpool + linear
// attention  ->  xr scratch (pixel-major)  ->  proj GEMM -> BN stats -> BN.
//
// Shapes: x (4,128,256,256) f32, qkv_w (384,32), proj_w (128,256),
//         gamma/beta (128). Output (4,128,256,256) f32.
//
// Coordinate collapse: roll(-2) on input and roll(+2) on output cancel:
// window (wh,ww) pixel (r,c) maps to image coord ((4wh+r+2)&255,(4ww+c+2)&255)
// for BOTH the x read and the final y write.
// ---------------------------------------------------------------------------

#define QSTR 392            // padded row stride for [pixel][384ch] smem tiles
#define OSTR 257            // padded row stride for [pixel][256ch] out tile
#define SMEM_ATT ((32*QSTR + 16*OSTR) * 4)   // 66624 bytes

// 268MB scratch: attention output, layout xr[pixel][256], pixel = b*65536+h*256+w
__device__ float g_xr[(size_t)262144 * 256];
__device__ float g_stat[256];   // [0:128) mean, [128:256) rsqrt(var+eps)

// ---------------------------------------------------------------------------
// Kernel 1: per-window fused qkv conv + pool + linear attention
// grid = 16384 blocks (one window), 128 threads
// ---------------------------------------------------------------------------
__global__ __launch_bounds__(128) void k_attn(
    const float* __restrict__ x, const float* __restrict__ qkv_w)
{
    extern __shared__ float sm[];
    float* s_qkv  = sm;                 // [16][QSTR] : qkv result, [pixel][oc]
    float* s_pool = sm + 16 * QSTR;     // [16][QSTR] : pooled
    float* s_c    = sm + 32 * QSTR;     // union region: s_x (2048) / s_out (16*OSTR)
    float* s_x    = s_c;                // [128ch][16px]
    float* s_out  = s_c;                // [16px][OSTR]

    const int t  = threadIdx.x;
    const int wid = blockIdx.x;
    const int b  = wid >> 12;
    const int wh = (wid >> 6) & 63;
    const int ww = wid & 63;
    const int h0 = wh * 4 + 2;
    const int w0 = ww * 4 + 2;

    // ---- load x window: 128 channels x 16 pixels --------------------------
#pragma unroll
    for (int it = 0; it < 16; ++it) {
        int idx = t + it * 128;          // 0..2047
        int c = idx >> 4, p = idx & 15;
        int h = (h0 + (p >> 2)) & 255;
        int w = (w0 + (p & 3)) & 255;
        s_x[idx] = x[(((size_t)(b * 128 + c)) << 16) + (h << 8) + w];
    }
    __syncthreads();

    // ---- grouped qkv conv: thread computes 6 oc x 8 px --------------------
    {
        const int ocb = t >> 1;
        const int oc0 = ocb * 6;                 // 6 | 96 so never crosses a group
        const int p0  = (t & 1) * 8;
        const int base_ic = (oc0 / 96) * 32;
        float acc[6][8];
#pragma unroll
        for (int u = 0; u < 6; ++u)
#pragma unroll
            for (int j = 0; j < 8; ++j) acc[u][j] = 0.f;
#pragma unroll 8
        for (int i = 0; i < 32; ++i) {
            const float4* xp4 = (const float4*)(&s_x[(base_ic + i) * 16 + p0]);
            float4 a = xp4[0], bb = xp4[1];
            float xv[8] = {a.x, a.y, a.z, a.w, bb.x, bb.y, bb.z, bb.w};
#pragma unroll
            for (int u = 0; u < 6; ++u) {
                float wv = __ldg(&qkv_w[(oc0 + u) * 32 + i]);
#pragma unroll
                for (int j = 0; j < 8; ++j)
                    acc[u][j] = fmaf(wv, xv[j], acc[u][j]);
            }
        }
#pragma unroll
        for (int u = 0; u < 6; ++u)
#pragma unroll
            for (int j = 0; j < 8; ++j)
                s_qkv[(p0 + j) * QSTR + oc0 + u] = acc[u][j];
    }
    __syncthreads();

    // ---- 5x5 zero-padded avg pool on 4x4, separable closed form -----------
#pragma unroll
    for (int u = 0; u < 3; ++u) {
        int oc = t + u * 128;
        float q[16];
#pragma unroll
        for (int p = 0; p < 16; ++p) q[p] = s_qkv[p * QSTR + oc];
        float cs[4];
#pragma unroll
        for (int c2 = 0; c2 < 4; ++c2) cs[c2] = q[c2] + q[4 + c2] + q[8 + c2] + q[12 + c2];
#pragma unroll
        for (int r = 0; r < 4; ++r) {
            float ra[4];
#pragma unroll
            for (int c2 = 0; c2 < 4; ++c2) {
                float v = cs[c2];
                if (r == 0) v -= q[12 + c2];   // rows 0..2
                if (r == 3) v -= q[c2];        // rows 1..3
                ra[c2] = v;
            }
            float T = ra[0] + ra[1] + ra[2] + ra[3];
            s_pool[(r * 4 + 0) * QSTR + oc] = (T - ra[3]) * 0.04f;
            s_pool[(r * 4 + 1) * QSTR + oc] = T * 0.04f;
            s_pool[(r * 4 + 2) * QSTR + oc] = T * 0.04f;
            s_pool[(r * 4 + 3) * QSTR + oc] = (T - ra[0]) * 0.04f;
        }
    }
    __syncthreads();

    // ---- linear attention: 32 groups, 4 lanes per group -------------------
    {
        const int g    = t >> 2;
        const int lsub = t & 3;
        const float* src = (g < 16) ? s_qkv : s_pool;   // warp-uniform
        const int gbase = (g & 15) * 24;

        float kv[72];                                   // kv[d][e], e=8 is ones-col
#pragma unroll
        for (int i = 0; i < 72; ++i) kv[i] = 0.f;
#pragma unroll
        for (int ll = 0; ll < 4; ++ll) {
            int l = lsub * 4 + ll;
            const float* row = src + l * QSTR + gbase;
            float kd[8], ve[8];
#pragma unroll
            for (int d = 0; d < 8; ++d) kd[d] = fmaxf(row[8 + d], 0.f);
#pragma unroll
            for (int e = 0; e < 8; ++e) ve[e] = row[16 + e];
#pragma unroll
            for (int d = 0; d < 8; ++d) {
#pragma unroll
                for (int e = 0; e < 8; ++e)
                    kv[d * 9 + e] = fmaf(kd[d], ve[e], kv[d * 9 + e]);
                kv[d * 9 + 8] += kd[d];
            }
        }
        // butterfly-reduce partial kv over the 4 lanes of this group
#pragma unroll
        for (int i = 0; i < 72; ++i) {
            float v = kv[i];
            v += __shfl_xor_sync(0xffffffffu, v, 1);
            v += __shfl_xor_sync(0xffffffffu, v, 2);
            kv[i] = v;
        }
#pragma unroll
        for (int ll = 0; ll < 4; ++ll) {
            int l = lsub * 4 + ll;
            const float* row = src + l * QSTR + gbase;
            float qd[8];
#pragma unroll
            for (int d = 0; d < 8; ++d) qd[d] = fmaxf(row[d], 0.f);
            float o[9];
#pragma unroll
            for (int e = 0; e < 9; ++e) {
                float s = 0.f;
#pragma unroll
                for (int d = 0; d < 8; ++d) s = fmaf(qd[d], kv[d * 9 + e], s);
                o[e] = s;
            }
            float inv = 1.0f / (o[8] + 1e-15f);
#pragma unroll
            for (int d = 0; d < 8; ++d)
                s_out[l * OSTR + g * 8 + d] = o[d] * inv;
        }
    }
    __syncthreads();

    // ---- write xr[pixel][256], pixel-major (ideal proj-GEMM A layout) -----
#pragma unroll
    for (int it = 0; it < 32; ++it) {
        int idx = t + it * 128;           // 0..4095
        int l = idx >> 8, c = idx & 255;
        int h = (h0 + (l >> 2)) & 255;
        int w = (w0 + (l & 3)) & 255;
        g_xr[((((size_t)b << 16) + (h << 8) + w) << 8) + c] = s_out[l * OSTR + c];
    }
}

// ---------------------------------------------------------------------------
// Kernel 2: proj GEMM  y[262144,128] = xr[262144,256] @ proj_w[128,256]^T
// grid = 2048, 256 threads; tile 128px x 128oc, K-chunk 32, 8x8 microtile
// ---------------------------------------------------------------------------
__global__ __launch_bounds__(256) void k_proj(
    const float* __restrict__ pw, float* __restrict__ y)
{
    __shared__ float As[32][128];   // [k][pixel]
    __shared__ float Bs[32][128];   // [k][oc]
    const int t  = threadIdx.x;
    const int tx = t & 15;          // pixel lane
    const int ty = t >> 4;          // oc lane
    const size_t m0 = (size_t)blockIdx.x * 128;
    const int row  = t >> 1;
    const int colh = (t & 1) * 16;

    float acc[8][8];
#pragma unroll
    for (int i = 0; i < 8; ++i)
#pragma unroll
        for (int j = 0; j < 8; ++j) acc[i][j] = 0.f;

    for (int k0 = 0; k0 < 256; k0 += 32) {
        const float4* sa = (const float4*)(g_xr + (m0 + row) * 256 + k0 + colh);
        const float4* sb = (const float4*)(pw + (size_t)row * 256 + k0 + colh);
#pragma unroll
        for (int qq = 0; qq < 4; ++qq) {
            float4 va = sa[qq];
            As[colh + qq * 4 + 0][row] = va.x;
            As[colh + qq * 4 + 1][row] = va.y;
            As[colh + qq * 4 + 2][row] = va.z;
            As[colh + qq * 4 + 3][row] = va.w;
            float4 vb = sb[qq];
            Bs[colh + qq * 4 + 0][row] = vb.x;
            Bs[colh + qq * 4 + 1][row] = vb.y;
            Bs[colh + qq * 4 + 2][row] = vb.z;
            Bs[colh + qq * 4 + 3][row] = vb.w;
        }
        __syncthreads();
#pragma unroll
        for (int k = 0; k < 32; ++k) {
            float a[8], bv[8];
#pragma unroll
            for (int i = 0; i < 8; ++i) a[i]  = As[k][tx + 16 * i];
#pragma unroll
            for (int j = 0; j < 8; ++j) bv[j] = Bs[k][ty + 16 * j];
#pragma unroll
            for (int i = 0; i < 8; ++i)
#pragma unroll
                for (int j = 0; j < 8; ++j)
                    acc[i][j] = fmaf(a[i], bv[j], acc[i][j]);
        }
        __syncthreads();
    }
    // epilogue: NCHW write
#pragma unroll
    for (int i = 0; i < 8; ++i) {
        size_t p   = m0 + tx + 16 * i;
        int bimg   = (int)(p >> 16);
        int inner  = (int)(p & 65535);
#pragma unroll
        for (int j = 0; j < 8; ++j) {
            int oc = ty + 16 * j;
            y[(((size_t)(bimg * 128 + oc)) << 16) + inner] = acc[i][j];
        }
    }
}

// ---------------------------------------------------------------------------
// Kernel 3: deterministic per-channel BN stats (1 block / channel)
// ---------------------------------------------------------------------------
__global__ __launch_bounds__(256) void k_stats(const float* __restrict__ y)
{
    __shared__ double ss[256], sq[256];
    const int c = blockIdx.x, t = threadIdx.x;
    float s = 0.f, s2 = 0.f;
#pragma unroll
    for (int b = 0; b < 4; ++b) {
        const float* pb = y + (((size_t)(b * 128 + c)) << 16);
        for (int i = t; i < 65536; i += 256) {
            float v = pb[i];
            s += v;
            s2 = fmaf(v, v, s2);
        }
    }
    ss[t] = (double)s; sq[t] = (double)s2;
    __syncthreads();
    for (int o = 128; o > 0; o >>= 1) {
        if (t < o) { ss[t] += ss[t + o]; sq[t] += sq[t + o]; }
        __syncthreads();
    }
    if (t == 0) {
        double mean = ss[0] / 262144.0;
        double var  = sq[0] / 262144.0 - mean * mean;
        g_stat[c]       = (float)mean;
        g_stat[128 + c] = (float)(1.0 / sqrt(var + 1e-5));
    }
}

// ---------------------------------------------------------------------------
// Kernel 4: apply BN in place (vectorized)
// ---------------------------------------------------------------------------
__global__ __launch_bounds__(256) void k_bn(
    float* __restrict__ y,
    const float* __restrict__ gamma, const float* __restrict__ beta)
{
    const size_t n4 = (size_t)33554432 / 4;
    for (size_t i = (size_t)blockIdx.x * blockDim.x + threadIdx.x; i < n4;
         i += (size_t)gridDim.x * blockDim.x) {
        float4 v = ((float4*)y)[i];
        int c = (int)((i >> 14) & 127);
        float mean = g_stat[c], inv = g_stat[128 + c];
        float sc = inv * __ldg(&gamma[c]);
        float sh = __ldg(&beta[c]) - mean * sc;
        v.x = fmaf(v.x, sc, sh);
        v.y = fmaf(v.y, sc, sh);
        v.z = fmaf(v.z, sc, sh);
        v.w = fmaf(v.w, sc, sh);
        ((float4*)y)[i] = v;
    }
}

// ---------------------------------------------------------------------------
extern "C" void kernel_launch(void* const* d_in, const int* in_sizes, int n_in,
                              void* d_out, int out_size)
{
    const float* x      = (const float*)d_in[0];
    const float* qkv_w  = (const float*)d_in[1];
    const float* proj_w = (const float*)d_in[2];
    const float* gamma  = (const float*)d_in[3];
    const float* beta   = (const float*)d_in[4];
    float* out = (float*)d_out;

    cudaFuncSetAttribute(k_attn, cudaFuncAttributeMaxDynamicSharedMemorySize,
                         SMEM_ATT);
    k_attn <<<16384, 128, SMEM_ATT>>>(x, qkv_w);
    k_proj <<<2048, 256>>>(proj_w, out);
    k_stats<<<128, 256>>>(out);
    k_bn   <<<2048, 256>>>(out, gamma, beta);
}

// round 6
// speedup vs baseline: 1.2580x; 1.2580x over previous
#include <cuda_runtime.h>
#include <cuda_bf16.h>
#include <stdint.h>
#include <stddef.h>
#include <math.h>

// ===========================================================================
// WindowsLite2MSA: fused windows + grouped qkv conv + 5x5 avgpool + linear
// attention -> bf16 hi/lo SW128 tile image -> mma.sync bf16 GEMM (3-term
// fp32-emulation, ldmatrix + cp.async pipeline) -> BN stats -> BN apply.
// (tcgen05 unavailable: harness targets plain sm_100.)
// ===========================================================================

#define QSTR 392
#define SMEM_ATT (32 * QSTR * 4)      // 50176 bytes
#define SWZ(x) ((x) ^ (((x) >> 3) & 0x70))

// X image: per (tile 0..2047)(chunk 0..3): [hi 16KB][lo 16KB], each a SW128
// [128 rows(px)][64 k bf16] tile. 268 MB total.
__device__ uint4 g_B4[16777216];
// W image: per (chunk 0..3): [hi 16KB][lo 16KB] of proj_w (oc rows). 128 KB.
__device__ uint4 g_A4[8192];
__device__ float g_ps [128 * 2048];
__device__ float g_ps2[128 * 2048];
__device__ float g_stat[256];

// ------------------------------ PTX helpers --------------------------------
__device__ __forceinline__ uint32_t smem_u32(const void* p) {
    uint32_t a;
    asm("{ .reg .u64 t; cvta.to.shared.u64 t, %1; cvt.u32.u64 %0, t; }"
        : "=r"(a) : "l"(p));
    return a;
}
__device__ __forceinline__ void ldm_x4(uint32_t* r, uint32_t addr) {
    asm volatile("ldmatrix.sync.aligned.m8n8.x4.shared.b16 {%0,%1,%2,%3}, [%4];"
                 : "=r"(r[0]), "=r"(r[1]), "=r"(r[2]), "=r"(r[3]) : "r"(addr));
}
__device__ __forceinline__ void mma16816(float* c, const uint32_t* a,
                                         const uint32_t* b) {
    asm volatile("mma.sync.aligned.m16n8k16.row.col.f32.bf16.bf16.f32 "
                 "{%0,%1,%2,%3}, {%4,%5,%6,%7}, {%8,%9}, {%0,%1,%2,%3};"
                 : "+f"(c[0]), "+f"(c[1]), "+f"(c[2]), "+f"(c[3])
                 : "r"(a[0]), "r"(a[1]), "r"(a[2]), "r"(a[3]),
                   "r"(b[0]), "r"(b[1]));
}
#define CPA(dst32, srcp) asm volatile( \
    "cp.async.cg.shared.global [%0], [%1], 16;" :: "r"(dst32), "l"(srcp) \
    : "memory")
#define CP_COMMIT() asm volatile("cp.async.commit_group;" ::: "memory")
#define CP_WAIT(n)  asm volatile("cp.async.wait_group %0;" :: "n"(n) : "memory")

// -------------------- bf16 hi/lo split + packing ---------------------------
__device__ __forceinline__ unsigned bfpair(__nv_bfloat16 a, __nv_bfloat16 b) {
    __nv_bfloat162 p = __halves2bfloat162(a, b);
    return *reinterpret_cast<unsigned*>(&p);
}
__device__ __forceinline__ void split8(const float* f, uint4& hi, uint4& lo) {
    __nv_bfloat16 hb[8];
    float rl[8];
#pragma unroll
    for (int j = 0; j < 8; ++j) {
        hb[j] = __float2bfloat16(f[j]);
        rl[j] = f[j] - __bfloat162float(hb[j]);
    }
    hi.x = bfpair(hb[0], hb[1]); hi.y = bfpair(hb[2], hb[3]);
    hi.z = bfpair(hb[4], hb[5]); hi.w = bfpair(hb[6], hb[7]);
    __nv_bfloat16 lb[8];
#pragma unroll
    for (int j = 0; j < 8; ++j) lb[j] = __float2bfloat16(rl[j]);
    lo.x = bfpair(lb[0], lb[1]); lo.y = bfpair(lb[2], lb[3]);
    lo.z = bfpair(lb[4], lb[5]); lo.w = bfpair(lb[6], lb[7]);
}

// ---------------------------------------------------------------------------
// k_prep: proj_w -> pre-swizzled bf16 hi/lo W image (4 chunks x [hi|lo] 16KB)
// ---------------------------------------------------------------------------
__global__ void k_prep(const float* __restrict__ pw) {
    int gid = blockIdx.x * blockDim.x + threadIdx.x;   // 0..4095
    int row = gid >> 5;          // oc 0..127
    int k0  = (gid & 31) * 8;    // 0..248
    float f[8];
#pragma unroll
    for (int j = 0; j < 8; ++j) f[j] = pw[row * 256 + k0 + j];
    uint4 hi, lo;
    split8(f, hi, lo);
    int chunk = k0 >> 6;
    int u = (k0 >> 3) & 7;
    size_t off = (size_t)chunk * 32768 + SWZ(row * 128 + u * 16);
    *(uint4*)((char*)g_A4 + off) = hi;
    *(uint4*)((char*)g_A4 + off + 16384) = lo;
}

// ---------------------------------------------------------------------------
// k_attn: per-window qkv conv + pool + linear attention; writes bf16 hi/lo
// directly into the SW128 X image.
// ---------------------------------------------------------------------------
__global__ __launch_bounds__(128) void k_attn(
    const float* __restrict__ x, const float* __restrict__ qkv_w)
{
    extern __shared__ float sm[];
    float* s_qkv  = sm;               // [16][QSTR]
    float* s_r2   = sm + 16 * QSTR;   // union: s_x (2048 f) then s_pool [16][QSTR]
    float* s_x    = s_r2;
    float* s_pool = s_r2;

    const int t   = threadIdx.x;
    const int wid = blockIdx.x;
    const int b   = wid >> 12;
    const int wh  = (wid >> 6) & 63;
    const int ww  = wid & 63;
    const int h0  = wh * 4 + 2;
    const int w0  = ww * 4 + 2;

    // ---- load x window: 128 ch x 16 px ------------------------------------
#pragma unroll
    for (int it = 0; it < 16; ++it) {
        int idx = t + it * 128;
        int c = idx >> 4, p = idx & 15;
        int h = (h0 + (p >> 2)) & 255;
        int w = (w0 + (p & 3)) & 255;
        s_x[idx] = x[(((size_t)(b * 128 + c)) << 16) + (h << 8) + w];
    }
    __syncthreads();

    // ---- grouped qkv conv: 6 oc x 8 px per thread -------------------------
    {
        const int oc0 = (t >> 1) * 6;
        const int p0  = (t & 1) * 8;
        const int base_ic = (oc0 / 96) * 32;
        float acc[6][8];
#pragma unroll
        for (int u = 0; u < 6; ++u)
#pragma unroll
            for (int j = 0; j < 8; ++j) acc[u][j] = 0.f;
#pragma unroll 8
        for (int i = 0; i < 32; ++i) {
            const float4* xp4 = (const float4*)(&s_x[(base_ic + i) * 16 + p0]);
            float4 a = xp4[0], bb = xp4[1];
            float xv[8] = {a.x, a.y, a.z, a.w, bb.x, bb.y, bb.z, bb.w};
#pragma unroll
            for (int u = 0; u < 6; ++u) {
                float wv = __ldg(&qkv_w[(oc0 + u) * 32 + i]);
#pragma unroll
                for (int j = 0; j < 8; ++j)
                    acc[u][j] = fmaf(wv, xv[j], acc[u][j]);
            }
        }
        __syncthreads();   // s_x dead before s_pool overwrites it
#pragma unroll
        for (int u = 0; u < 6; ++u)
#pragma unroll
            for (int j = 0; j < 8; ++j)
                s_qkv[(p0 + j) * QSTR + oc0 + u] = acc[u][j];
    }
    __syncthreads();

    // ---- 5x5 zero-padded avgpool, separable closed form -------------------
#pragma unroll
    for (int u = 0; u < 3; ++u) {
        int oc = t + u * 128;
        float q[16];
#pragma unroll
        for (int p = 0; p < 16; ++p) q[p] = s_qkv[p * QSTR + oc];
        float cs[4];
#pragma unroll
        for (int c2 = 0; c2 < 4; ++c2) cs[c2] = q[c2] + q[4 + c2] + q[8 + c2] + q[12 + c2];
#pragma unroll
        for (int r = 0; r < 4; ++r) {
            float ra[4];
#pragma unroll
            for (int c2 = 0; c2 < 4; ++c2) {
                float v = cs[c2];
                if (r == 0) v -= q[12 + c2];
                if (r == 3) v -= q[c2];
                ra[c2] = v;
            }
            float T = ra[0] + ra[1] + ra[2] + ra[3];
            s_pool[(r * 4 + 0) * QSTR + oc] = (T - ra[3]) * 0.04f;
            s_pool[(r * 4 + 1) * QSTR + oc] = T * 0.04f;
            s_pool[(r * 4 + 2) * QSTR + oc] = T * 0.04f;
            s_pool[(r * 4 + 3) * QSTR + oc] = (T - ra[0]) * 0.04f;
        }
    }
    __syncthreads();

    // ---- linear attention, write bf16 hi/lo tiles directly ----------------
    {
        const int g    = t >> 2;
        const int lsub = t & 3;
        const float* src = (g < 16) ? s_qkv : s_pool;    // warp-uniform
        const int gbase = (g & 15) * 24;
        const int cB = g >> 3;       // K-chunk of the X image
        const int uB = g & 7;        // 16B unit within 128B row

        float kv[72];
#pragma unroll
        for (int i = 0; i < 72; ++i) kv[i] = 0.f;
#pragma unroll
        for (int ll = 0; ll < 4; ++ll) {
            int l = lsub * 4 + ll;
            const float* row = src + l * QSTR + gbase;
            float kd[8], ve[8];
#pragma unroll
            for (int d = 0; d < 8; ++d) kd[d] = fmaxf(row[8 + d], 0.f);
#pragma unroll
            for (int e = 0; e < 8; ++e) ve[e] = row[16 + e];
#pragma unroll
            for (int d = 0; d < 8; ++d) {
#pragma unroll
                for (int e = 0; e < 8; ++e)
                    kv[d * 9 + e] = fmaf(kd[d], ve[e], kv[d * 9 + e]);
                kv[d * 9 + 8] += kd[d];
            }
        }
#pragma unroll
        for (int i = 0; i < 72; ++i) {
            float v = kv[i];
            v += __shfl_xor_sync(0xffffffffu, v, 1);
            v += __shfl_xor_sync(0xffffffffu, v, 2);
            kv[i] = v;
        }
#pragma unroll
        for (int ll = 0; ll < 4; ++ll) {
            int l = lsub * 4 + ll;
            const float* row = src + l * QSTR + gbase;
            float qd[8];
#pragma unroll
            for (int d = 0; d < 8; ++d) qd[d] = fmaxf(row[d], 0.f);
            float o[9];
#pragma unroll
            for (int e = 0; e < 9; ++e) {
                float s = 0.f;
#pragma unroll
                for (int d = 0; d < 8; ++d) s = fmaf(qd[d], kv[d * 9 + e], s);
                o[e] = s;
            }
            float inv = 1.0f / (o[8] + 1e-15f);
            float f[8];
#pragma unroll
            for (int d = 0; d < 8; ++d) f[d] = o[d] * inv;

            int h = (h0 + lsub) & 255;
            int w = (w0 + ll) & 255;
            int px = (b << 16) + (h << 8) + w;
            int tile = px >> 7, prow = px & 127;
            size_t rb = ((size_t)(tile * 4 + cB) * 2) * 16384
                      + (size_t)SWZ(prow * 128 + uB * 16);
            uint4 hi, lo;
            split8(f, hi, lo);
            *(uint4*)((char*)g_B4 + rb)          = hi;
            *(uint4*)((char*)g_B4 + rb + 16384)  = lo;
        }
    }
}

// ---------------------------------------------------------------------------
// k_proj: mma.sync bf16 3-term GEMM.  y[px][oc] = xr[px][k] * w[oc][k]^T.
// Per CTA: 128px x 128oc, K=256 in 4 chunks of 64; cp.async double-buffered.
// 8 warps: warp (wm,wc) computes 32px x 64oc with m16n8k16 fragments.
// ---------------------------------------------------------------------------
#define PROJ_SMEM 131072   // two 64KB chunk buffers; epilogue reuses 67.6KB

__global__ __launch_bounds__(256, 1) void k_proj(float* __restrict__ y)
{
    extern __shared__ __align__(16) unsigned char psm[];
    const uint32_t sbase = smem_u32(psm);
    const int t = threadIdx.x, lane = t & 31, w = t >> 5;
    const int wm = w & 3, wc = w >> 2;     // warp px-block / oc-block

    float acc[2][8][4];
#pragma unroll
    for (int a = 0; a < 2; ++a)
#pragma unroll
        for (int b = 0; b < 8; ++b)
#pragma unroll
            for (int c = 0; c < 4; ++c) acc[a][b][c] = 0.f;

    // ---- cp.async chunk copy: [W hi|lo 32KB][X hi|lo 32KB] ----------------
    const uint4* Xsrc = g_B4 + (size_t)blockIdx.x * 8192;
#define ISSUE(buf, ck) do {                                                    \
        const uint4* _As = g_A4 + (ck) * 2048;                                 \
        const uint4* _Bs = Xsrc + (ck) * 2048;                                 \
        uint32_t _d = sbase + (buf) * 65536;                                   \
        _Pragma("unroll")                                                      \
        for (int _i = 0; _i < 8; ++_i)                                         \
            CPA(_d + (uint32_t)(t + _i * 256) * 16u,                           \
                (const void*)(_As + t + _i * 256));                            \
        _Pragma("unroll")                                                      \
        for (int _i = 0; _i < 8; ++_i)                                         \
            CPA(_d + 32768u + (uint32_t)(t + _i * 256) * 16u,                  \
                (const void*)(_Bs + t + _i * 256));                            \
    } while (0)

    ISSUE(0, 0); CP_COMMIT();
    ISSUE(1, 1); CP_COMMIT();

    // lane-derived ldmatrix address components
    const int pxo = ((lane >> 3) & 1) * 8 + (lane & 7);   // A(x) frags
    const int axu = lane >> 4;
    const int oco = ((lane >> 4) * 8) + (lane & 7);       // B(w) frags
    const int bxu = (lane >> 3) & 1;

    for (int c = 0; c < 4; ++c) {
        if (c < 3) { CP_WAIT(1); } else { CP_WAIT(0); }
        __syncthreads();

        const uint32_t d  = sbase + (uint32_t)(c & 1) * 65536u;
        const uint32_t Wh = d, Wl = d + 16384, Xh = d + 32768, Xl = d + 49152;

#pragma unroll
        for (int ks = 0; ks < 4; ++ks) {
            uint32_t xh[2][4], xl[2][4];
#pragma unroll
            for (int mi = 0; mi < 2; ++mi) {
                uint32_t off = SWZ((uint32_t)((wm * 32 + mi * 16 + pxo) * 128
                                              + (ks * 2 + axu) * 16));
                ldm_x4(xh[mi], Xh + off);
                ldm_x4(xl[mi], Xl + off);
            }
#pragma unroll
            for (int bi = 0; bi < 4; ++bi) {
                uint32_t off = SWZ((uint32_t)((wc * 64 + bi * 16 + oco) * 128
                                              + (ks * 2 + bxu) * 16));
                uint32_t wh[4], wl[4];
                ldm_x4(wh, Wh + off);
                ldm_x4(wl, Wl + off);
#pragma unroll
                for (int mi = 0; mi < 2; ++mi)
#pragma unroll
                    for (int sub = 0; sub < 2; ++sub) {
                        float* a = acc[mi][bi * 2 + sub];
                        mma16816(a, xh[mi], wh + sub * 2);
                        mma16816(a, xh[mi], wl + sub * 2);
                        mma16816(a, xl[mi], wh + sub * 2);
                    }
            }
        }
        __syncthreads();
        if (c < 2) { ISSUE(c & 1, c + 2); CP_COMMIT(); }
    }

    // ---- epilogue: acc -> smem [oc][132] -> y + stats partials ------------
    float* es = (float*)psm;
    const int gg = lane >> 2, tg = lane & 3;
#pragma unroll
    for (int mi = 0; mi < 2; ++mi)
#pragma unroll
        for (int fi = 0; fi < 8; ++fi) {
            int px = wm * 32 + mi * 16 + gg;
            int oc = wc * 64 + fi * 8 + 2 * tg;
            es[oc * 132 + px]             = acc[mi][fi][0];
            es[(oc + 1) * 132 + px]       = acc[mi][fi][1];
            es[oc * 132 + px + 8]         = acc[mi][fi][2];
            es[(oc + 1) * 132 + px + 8]   = acc[mi][fi][3];
        }
    __syncthreads();

    const int row = t >> 1, half = t & 1;
    const float4* src4 = (const float4*)(es + row * 132 + half * 64);
    const size_t px0 = (size_t)blockIdx.x * 128;
    const int bimg = (int)(px0 >> 16);
    float* dst = y + (((size_t)(bimg * 128 + row)) << 16) + (px0 & 65535)
               + half * 64;
    float s = 0.f, s2 = 0.f;
#pragma unroll
    for (int q = 0; q < 16; ++q) {
        float4 v = src4[q];
        s = s + v.x + v.y + v.z + v.w;
        s2 = fmaf(v.x, v.x, s2); s2 = fmaf(v.y, v.y, s2);
        s2 = fmaf(v.z, v.z, s2); s2 = fmaf(v.w, v.w, s2);
        ((float4*)dst)[q] = v;
    }
    s  += __shfl_xor_sync(0xffffffffu, s, 1);
    s2 += __shfl_xor_sync(0xffffffffu, s2, 1);
    if (half == 0) {
        g_ps [row * 2048 + blockIdx.x] = s;
        g_ps2[row * 2048 + blockIdx.x] = s2;
    }
}

// ---------------------------------------------------------------------------
// k_stats: deterministic reduction of per-tile partials, 1 block / channel
// ---------------------------------------------------------------------------
__global__ __launch_bounds__(256) void k_stats()
{
    __shared__ double ss[256], sq[256];
    const int c = blockIdx.x, t = threadIdx.x;
    double s = 0.0, s2 = 0.0;
#pragma unroll
    for (int k = 0; k < 8; ++k) {
        int i = t + k * 256;
        s  += (double)g_ps [c * 2048 + i];
        s2 += (double)g_ps2[c * 2048 + i];
    }
    ss[t] = s; sq[t] = s2;
    __syncthreads();
    for (int o = 128; o > 0; o >>= 1) {
        if (t < o) { ss[t] += ss[t + o]; sq[t] += sq[t + o]; }
        __syncthreads();
    }
    if (t == 0) {
        double mean = ss[0] / 262144.0;
        double var  = sq[0] / 262144.0 - mean * mean;
        g_stat[c]       = (float)mean;
        g_stat[128 + c] = (float)(1.0 / sqrt(var + 1e-5));
    }
}

// ---------------------------------------------------------------------------
// k_bn: apply BN in place
// ---------------------------------------------------------------------------
__global__ __launch_bounds__(256) void k_bn(
    float* __restrict__ y,
    const float* __restrict__ gamma, const float* __restrict__ beta)
{
    const size_t n4 = (size_t)33554432 / 4;
    for (size_t i = (size_t)blockIdx.x * blockDim.x + threadIdx.x; i < n4;
         i += (size_t)gridDim.x * blockDim.x) {
        float4 v = ((float4*)y)[i];
        int c = (int)((i >> 14) & 127);
        float mean = g_stat[c], inv = g_stat[128 + c];
        float sc = inv * __ldg(&gamma[c]);
        float sh = __ldg(&beta[c]) - mean * sc;
        v.x = fmaf(v.x, sc, sh);
        v.y = fmaf(v.y, sc, sh);
        v.z = fmaf(v.z, sc, sh);
        v.w = fmaf(v.w, sc, sh);
        ((float4*)y)[i] = v;
    }
}

// ---------------------------------------------------------------------------
extern "C" void kernel_launch(void* const* d_in, const int* in_sizes, int n_in,
                              void* d_out, int out_size)
{
    const float* x      = (const float*)d_in[0];
    const float* qkv_w  = (const float*)d_in[1];
    const float* proj_w = (const float*)d_in[2];
    const float* gamma  = (const float*)d_in[3];
    const float* beta   = (const float*)d_in[4];
    float* out = (float*)d_out;

    cudaFuncSetAttribute(k_attn, cudaFuncAttributeMaxDynamicSharedMemorySize,
                         SMEM_ATT);
    cudaFuncSetAttribute(k_proj, cudaFuncAttributeMaxDynamicSharedMemorySize,
                         PROJ_SMEM);

    k_prep <<<16, 256>>>(proj_w);
    k_attn <<<16384, 128, SMEM_ATT>>>(x, qkv_w);
    k_proj <<<2048, 256, PROJ_SMEM>>>(out);
    k_stats<<<128, 256>>>();
    k_bn   <<<2048, 256>>>(out, gamma, beta);
}